// round 1
// baseline (speedup 1.0000x reference)
#include <cuda_runtime.h>
#include <cstdint>
#include <cstdio>

// Problem constants (fixed by the benchmark)
#define NN   50000
#define DD   128
#define LL   3
#define GG   16
#define OUTD 2

// ---------------- static device scratch (no allocation allowed) ----------------
__device__ float g_bufA[2][(size_t)NN * DD];   // ping
__device__ float g_bufB[2][(size_t)NN * DD];   // pong
__device__ float g_agg[(size_t)NN * DD];       // neighbor-sum scratch (reused)
__device__ float g_inv[2][NN];                 // 1/max(cnt,1)
__device__ int   g_cnt[2][NN];
__device__ float g_pool[2][GG][DD];
__device__ int   g_pcnt[2][GG];

// ---------------- kernels ----------------

// generic zero (float4 granularity; n4 = count of float4)
__global__ void zero_kernel(float4* p, size_t n4) {
    size_t i = blockIdx.x * (size_t)blockDim.x + threadIdx.x;
    size_t stride = (size_t)gridDim.x * blockDim.x;
    float4 z = make_float4(0.f, 0.f, 0.f, 0.f);
    for (; i < n4; i += stride) p[i] = z;
}

// in-degree count per node
__global__ void count_kernel(const int* __restrict__ dst, int E, int* __restrict__ cnt) {
    int i = blockIdx.x * blockDim.x + threadIdx.x;
    int stride = gridDim.x * blockDim.x;
    for (; i < E; i += stride) atomicAdd(&cnt[dst[i]], 1);
}

__global__ void inv_kernel(const int* __restrict__ cnt, float* __restrict__ inv, int n) {
    int i = blockIdx.x * blockDim.x + threadIdx.x;
    if (i < n) {
        int c = cnt[i];
        inv[i] = 1.0f / (float)(c > 0 ? c : 1);
    }
}

// warp-per-edge scatter: agg[dst] += x[src]   (vectorized L2 reduction)
__global__ void scatter_kernel(const float* __restrict__ x,
                               const int* __restrict__ src,
                               const int* __restrict__ dst,
                               int E, float* __restrict__ agg) {
    int warp = (blockIdx.x * blockDim.x + threadIdx.x) >> 5;
    int lane = threadIdx.x & 31;
    int nwarps = (gridDim.x * blockDim.x) >> 5;
    const float4* x4 = (const float4*)x;
    for (int e = warp; e < E; e += nwarps) {
        int s = src[e];
        int d = dst[e];
        float4 v = x4[(size_t)s * 32 + lane];
        float* a = agg + (size_t)d * DD + lane * 4;
        asm volatile("red.global.add.v4.f32 [%0], {%1,%2,%3,%4};"
                     :: "l"(a), "f"(v.x), "f"(v.y), "f"(v.z), "f"(v.w)
                     : "memory");
    }
}

// Fused SAGE layer GEMM:
//   out[r,:] = relu( (agg[r,:]*inv[r]) @ Wl + x[r,:] @ Wr + b )
// Treated as C = A'[N,256] @ W'[256,128],  A' = [agg*inv | x],  W' = [Wl ; Wr]
#define BM 128
#define BN 128
#define BK 8
__global__ __launch_bounds__(256, 2)
void gemm_kernel(const float* __restrict__ agg, const float* __restrict__ inv,
                 const float* __restrict__ xin,
                 const float* __restrict__ Wlp, const float* __restrict__ Wrp,
                 const float* __restrict__ bias,
                 float* __restrict__ out, int n) {
    __shared__ float As[BK][BM];
    __shared__ float Ws[BK][BN];
    int tid = threadIdx.x;            // 256 threads
    int row0 = blockIdx.x * BM;
    int tx = tid & 15;                // 16 col-groups of 8
    int ty = tid >> 4;                // 16 row-groups of 8
    float acc[8][8];
#pragma unroll
    for (int i = 0; i < 8; i++)
#pragma unroll
        for (int j = 0; j < 8; j++) acc[i][j] = 0.f;

    int arow = tid >> 1;              // 0..127
    int akoff = (tid & 1) * 4;        // 0 or 4
    int wrow = tid >> 5;              // 0..7
    int wcol = (tid & 31) * 4;        // 0..124

    for (int kb = 0; kb < 2 * DD; kb += BK) {
        // --- load A' slab (128 rows x 8 k) transposed into As ---
        int grow = row0 + arow;
        float4 av = make_float4(0.f, 0.f, 0.f, 0.f);
        int k = kb + akoff;
        if (grow < n) {
            if (k < DD) {
                av = *(const float4*)(agg + (size_t)grow * DD + k);
                float iv = inv[grow];
                av.x *= iv; av.y *= iv; av.z *= iv; av.w *= iv;
            } else {
                av = *(const float4*)(xin + (size_t)grow * DD + (k - DD));
            }
        }
        As[akoff + 0][arow] = av.x;
        As[akoff + 1][arow] = av.y;
        As[akoff + 2][arow] = av.z;
        As[akoff + 3][arow] = av.w;

        // --- load W' slab (8 k x 128 cols) ---
        int wk = kb + wrow;
        float4 wv = (wk < DD) ? *(const float4*)(Wlp + (size_t)wk * DD + wcol)
                              : *(const float4*)(Wrp + (size_t)(wk - DD) * DD + wcol);
        *(float4*)&Ws[wrow][wcol] = wv;

        __syncthreads();
#pragma unroll
        for (int kk = 0; kk < BK; kk++) {
            float a[8], b[8];
            *(float4*)(a)     = *(float4*)&As[kk][ty * 8];
            *(float4*)(a + 4) = *(float4*)&As[kk][ty * 8 + 4];
            *(float4*)(b)     = *(float4*)&Ws[kk][tx * 8];
            *(float4*)(b + 4) = *(float4*)&Ws[kk][tx * 8 + 4];
#pragma unroll
            for (int i = 0; i < 8; i++)
#pragma unroll
                for (int j = 0; j < 8; j++)
                    acc[i][j] += a[i] * b[j];
        }
        __syncthreads();
    }

    // epilogue: bias + relu
#pragma unroll
    for (int i = 0; i < 8; i++) {
        int r = row0 + ty * 8 + i;
        if (r >= n) break;
#pragma unroll
        for (int j = 0; j < 8; j += 4) {
            int c = tx * 8 + j;
            float4 v;
            v.x = fmaxf(acc[i][j + 0] + bias[c + 0], 0.f);
            v.y = fmaxf(acc[i][j + 1] + bias[c + 1], 0.f);
            v.z = fmaxf(acc[i][j + 2] + bias[c + 2], 0.f);
            v.w = fmaxf(acc[i][j + 3] + bias[c + 3], 0.f);
            *(float4*)(out + (size_t)r * DD + c) = v;
        }
    }
}

// mean-pool partials: exploits sorted batch[] -> register accumulate, flush on change
#define ROWS_PB 512
__global__ void pool_kernel(const float* __restrict__ x, const int* __restrict__ batch,
                            int n, float* __restrict__ pool, int* __restrict__ pcnt) {
    int c = threadIdx.x;              // 0..127
    int r0 = blockIdx.x * ROWS_PB;
    if (r0 >= n) return;
    int r1 = min(r0 + ROWS_PB, n);
    float acc = 0.f;
    int cnt = 0;
    int gcur = batch[r0];
    for (int r = r0; r < r1; r++) {
        int g = batch[r];
        if (g != gcur) {
            atomicAdd(&pool[(size_t)gcur * DD + c], acc);
            if (c == 0) atomicAdd(&pcnt[gcur], cnt);
            acc = 0.f; cnt = 0; gcur = g;
        }
        acc += x[(size_t)r * DD + c];
        cnt++;
    }
    atomicAdd(&pool[(size_t)gcur * DD + c], acc);
    if (c == 0) atomicAdd(&pcnt[gcur], cnt);
}

// final: mean-normalize pools, concat, tiny [16,256]@[256,2] + bias
__global__ void final_kernel(const float* __restrict__ linW, const float* __restrict__ linb,
                             float* __restrict__ out) {
    int t32 = threadIdx.x;
    if (t32 >= GG * OUTD) return;
    int g = t32 / OUTD;
    int o = t32 % OUTD;
    float s = linb[o];
    for (int t = 0; t < 2; t++) {
        float ic = 1.0f / fmaxf((float)g_pcnt[t][g], 1.0f);
        const float* p = &g_pool[t][g][0];
        for (int c = 0; c < DD; c++)
            s += p[c] * ic * linW[(t * DD + c) * OUTD + o];
    }
    out[g * OUTD + o] = s;
}

// ---------------- launch ----------------
extern "C" void kernel_launch(void* const* d_in, const int* in_sizes, int n_in,
                              void* d_out, int out_size) {
    const float* x_void   = (const float*)d_in[0];
    const float* x_vessel = (const float*)d_in[1];
    const float* Wl   = (const float*)d_in[2];   // [L,2,D,D]
    const float* bl   = (const float*)d_in[3];   // [L,2,D]
    const float* Wr   = (const float*)d_in[4];   // [L,2,D,D]
    const float* linW = (const float*)d_in[5];   // [2D,OUT]
    const float* linb = (const float*)d_in[6];   // [OUT]
    const int* edge_void   = (const int*)d_in[7];   // [2,E]
    const int* edge_vessel = (const int*)d_in[8];
    const int* batch_void   = (const int*)d_in[9];  // [N]
    const int* batch_vessel = (const int*)d_in[10];

    const int n = in_sizes[9];              // 50000
    const int E = in_sizes[7] / 2;          // 800000

    float *bufA, *bufB, *aggp, *invp, *poolp;
    int *cntp, *pcntp;
    cudaGetSymbolAddress((void**)&bufA, g_bufA);
    cudaGetSymbolAddress((void**)&bufB, g_bufB);
    cudaGetSymbolAddress((void**)&aggp, g_agg);
    cudaGetSymbolAddress((void**)&invp, g_inv);
    cudaGetSymbolAddress((void**)&cntp, g_cnt);
    cudaGetSymbolAddress((void**)&poolp, g_pool);
    cudaGetSymbolAddress((void**)&pcntp, g_pcnt);

    const int ZB = 1024, ZT = 256;

    // zero counts + pools (int zero == float zero bit pattern)
    zero_kernel<<<64, ZT>>>((float4*)cntp, (size_t)(2 * NN) / 4);
    zero_kernel<<<4, ZT>>>((float4*)poolp, (size_t)(2 * GG * DD) / 4);
    zero_kernel<<<1, 32>>>((float4*)pcntp, (size_t)(2 * GG) / 4);

    // in-degree counts (edge-structure only; same every layer)
    count_kernel<<<512, 256>>>(edge_void + E,   E, cntp);
    count_kernel<<<512, 256>>>(edge_vessel + E, E, cntp + NN);
    inv_kernel<<<(2 * n + 255) / 256, 256>>>(cntp, invp, 2 * n);

    const float* cur[2] = { x_void, x_vessel };
    float* pingA[2] = { bufA, bufA + (size_t)NN * DD };
    float* pingB[2] = { bufB, bufB + (size_t)NN * DD };

    const int gemm_blocks = (n + BM - 1) / BM;

    for (int l = 0; l < LL; l++) {
        for (int t = 0; t < 2; t++) {
            const int* edges = (t == 0) ? edge_void : edge_vessel;
            float* nxt = (l & 1) ? pingB[t] : pingA[t];

            zero_kernel<<<ZB, ZT>>>((float4*)aggp, (size_t)n * DD / 4);
            scatter_kernel<<<2048, 256>>>(cur[t], edges, edges + E, E, aggp);

            const float* Wlp = Wl + ((size_t)(l * 2 + t)) * DD * DD;
            const float* Wrp = Wr + ((size_t)(l * 2 + t)) * DD * DD;
            const float* blp = bl + ((size_t)(l * 2 + t)) * DD;
            gemm_kernel<<<gemm_blocks, 256>>>(aggp, invp + t * NN, cur[t],
                                              Wlp, Wrp, blp, nxt, n);
            cur[t] = nxt;
        }
    }

    // pooling
    int pblocks = (n + ROWS_PB - 1) / ROWS_PB;
    pool_kernel<<<pblocks, DD>>>(cur[0], batch_void,   n, poolp,               pcntp);
    pool_kernel<<<pblocks, DD>>>(cur[1], batch_vessel, n, poolp + GG * DD,     pcntp + GG);

    final_kernel<<<1, 32>>>(linW, linb, (float*)d_out);
}

// round 2
// speedup vs baseline: 1.8533x; 1.8533x over previous
#include <cuda_runtime.h>
#include <cstdint>

// Problem constants (fixed by the benchmark)
#define NN   50000
#define EE   800000
#define DD   128
#define LL   3
#define GG   16
#define OUTD 2

// ---------------- static device scratch (no allocation allowed) ----------------
__device__ float g_bufA[2][(size_t)NN * DD];     // ping
__device__ float g_bufB[2][(size_t)NN * DD];     // pong
__device__ float g_mean[2][(size_t)NN * DD];     // per-type aggregated mean
__device__ int   g_cnt[2][NN];                   // in-degree histogram
__device__ int   g_rowptr[2][NN + 1];            // CSR row pointers
__device__ int   g_cursor[2][NN];                // fill cursors
__device__ int   g_csr[2][EE];                   // CSR column (src) indices
__device__ float g_pool[2][GG][DD];
__device__ int   g_pcnt[2][GG];

// ---------------- kernels ----------------

__global__ void zero_kernel(float4* p, size_t n4) {
    size_t i = blockIdx.x * (size_t)blockDim.x + threadIdx.x;
    size_t stride = (size_t)gridDim.x * blockDim.x;
    float4 z = make_float4(0.f, 0.f, 0.f, 0.f);
    for (; i < n4; i += stride) p[i] = z;
}

// in-degree histogram
__global__ void count_kernel(const int* __restrict__ dst, int E, int* __restrict__ cnt) {
    int i = blockIdx.x * blockDim.x + threadIdx.x;
    int stride = gridDim.x * blockDim.x;
    for (; i < E; i += stride) atomicAdd(&cnt[dst[i]], 1);
}

// single-block exclusive scan of cnt[0..n) -> rowptr[0..n], rowptr[n]=total
__global__ void scan_kernel(const int* __restrict__ cnt, int n, int* __restrict__ rowptr) {
    __shared__ int part[1024];
    int t = threadIdx.x;
    int chunk = (n + 1023) / 1024;
    int beg = t * chunk;
    int end = min(beg + chunk, n);
    int s = 0;
    for (int i = beg; i < end; i++) s += cnt[i];
    part[t] = s;
    __syncthreads();
    // Hillis-Steele inclusive scan
    for (int off = 1; off < 1024; off <<= 1) {
        int v = (t >= off) ? part[t - off] : 0;
        __syncthreads();
        part[t] += v;
        __syncthreads();
    }
    int run = (t == 0) ? 0 : part[t - 1];
    for (int i = beg; i < end; i++) { rowptr[i] = run; run += cnt[i]; }
    if (t == 0) rowptr[n] = part[1023];
}

__global__ void copy_int_kernel(const int* __restrict__ src, int* __restrict__ dst, int n) {
    int i = blockIdx.x * blockDim.x + threadIdx.x;
    if (i < n) dst[i] = src[i];
}

// CSR fill: for each edge, place src into its dst's slot
__global__ void fill_kernel(const int* __restrict__ src, const int* __restrict__ dst,
                            int E, int* __restrict__ cursor, int* __restrict__ csr) {
    int i = blockIdx.x * blockDim.x + threadIdx.x;
    int stride = gridDim.x * blockDim.x;
    for (; i < E; i += stride) {
        int d = dst[i];
        int pos = atomicAdd(&cursor[d], 1);
        csr[pos] = src[i];
    }
}

// warp-per-node gather + mean:  mean[i,:] = (1/max(deg,1)) * sum_j x[csr[j],:]
__global__ void gather_mean_kernel(const float* __restrict__ x,
                                   const int* __restrict__ rowptr,
                                   const int* __restrict__ csr,
                                   int n, float* __restrict__ mean) {
    int warp = (blockIdx.x * blockDim.x + threadIdx.x) >> 5;
    int lane = threadIdx.x & 31;
    int nwarps = (gridDim.x * blockDim.x) >> 5;
    const float4* x4 = (const float4*)x;
    for (int node = warp; node < n; node += nwarps) {
        int b = rowptr[node];
        int e = rowptr[node + 1];
        float4 a0 = make_float4(0.f, 0.f, 0.f, 0.f);
        float4 a1 = a0;
        int j = b;
        for (; j + 1 < e; j += 2) {
            int s0 = __ldg(&csr[j]);
            int s1 = __ldg(&csr[j + 1]);
            float4 v0 = x4[(size_t)s0 * 32 + lane];
            float4 v1 = x4[(size_t)s1 * 32 + lane];
            a0.x += v0.x; a0.y += v0.y; a0.z += v0.z; a0.w += v0.w;
            a1.x += v1.x; a1.y += v1.y; a1.z += v1.z; a1.w += v1.w;
        }
        if (j < e) {
            int s0 = __ldg(&csr[j]);
            float4 v0 = x4[(size_t)s0 * 32 + lane];
            a0.x += v0.x; a0.y += v0.y; a0.z += v0.z; a0.w += v0.w;
        }
        float ic = 1.0f / (float)max(e - b, 1);
        float4 r;
        r.x = (a0.x + a1.x) * ic;
        r.y = (a0.y + a1.y) * ic;
        r.z = (a0.z + a1.z) * ic;
        r.w = (a0.w + a1.w) * ic;
        ((float4*)mean)[(size_t)node * 32 + lane] = r;
    }
}

// Fused SAGE layer GEMM:
//   out[r,:] = relu( mean[r,:] @ Wl + x[r,:] @ Wr + b )
// C = A'[N,256] @ W'[256,128],  A' = [mean | x],  W' = [Wl ; Wr]
#define BM 128
#define BN 128
#define BK 8
__global__ __launch_bounds__(256, 2)
void gemm_kernel(const float* __restrict__ mean,
                 const float* __restrict__ xin,
                 const float* __restrict__ Wlp, const float* __restrict__ Wrp,
                 const float* __restrict__ bias,
                 float* __restrict__ out, int n) {
    __shared__ float As[BK][BM];
    __shared__ float Ws[BK][BN];
    int tid = threadIdx.x;            // 256 threads
    int row0 = blockIdx.x * BM;
    int tx = tid & 15;
    int ty = tid >> 4;
    float acc[8][8];
#pragma unroll
    for (int i = 0; i < 8; i++)
#pragma unroll
        for (int j = 0; j < 8; j++) acc[i][j] = 0.f;

    int arow = tid >> 1;              // 0..127
    int akoff = (tid & 1) * 4;        // 0 or 4
    int wrow = tid >> 5;              // 0..7
    int wcol = (tid & 31) * 4;        // 0..124

    for (int kb = 0; kb < 2 * DD; kb += BK) {
        int grow = row0 + arow;
        float4 av = make_float4(0.f, 0.f, 0.f, 0.f);
        int k = kb + akoff;
        if (grow < n) {
            av = (k < DD) ? *(const float4*)(mean + (size_t)grow * DD + k)
                          : *(const float4*)(xin  + (size_t)grow * DD + (k - DD));
        }
        As[akoff + 0][arow] = av.x;
        As[akoff + 1][arow] = av.y;
        As[akoff + 2][arow] = av.z;
        As[akoff + 3][arow] = av.w;

        int wk = kb + wrow;
        float4 wv = (wk < DD) ? *(const float4*)(Wlp + (size_t)wk * DD + wcol)
                              : *(const float4*)(Wrp + (size_t)(wk - DD) * DD + wcol);
        *(float4*)&Ws[wrow][wcol] = wv;

        __syncthreads();
#pragma unroll
        for (int kk = 0; kk < BK; kk++) {
            float a[8], b[8];
            *(float4*)(a)     = *(float4*)&As[kk][ty * 8];
            *(float4*)(a + 4) = *(float4*)&As[kk][ty * 8 + 4];
            *(float4*)(b)     = *(float4*)&Ws[kk][tx * 8];
            *(float4*)(b + 4) = *(float4*)&Ws[kk][tx * 8 + 4];
#pragma unroll
            for (int i = 0; i < 8; i++)
#pragma unroll
                for (int j = 0; j < 8; j++)
                    acc[i][j] += a[i] * b[j];
        }
        __syncthreads();
    }

#pragma unroll
    for (int i = 0; i < 8; i++) {
        int r = row0 + ty * 8 + i;
        if (r >= n) break;
#pragma unroll
        for (int j = 0; j < 8; j += 4) {
            int c = tx * 8 + j;
            float4 v;
            v.x = fmaxf(acc[i][j + 0] + bias[c + 0], 0.f);
            v.y = fmaxf(acc[i][j + 1] + bias[c + 1], 0.f);
            v.z = fmaxf(acc[i][j + 2] + bias[c + 2], 0.f);
            v.w = fmaxf(acc[i][j + 3] + bias[c + 3], 0.f);
            *(float4*)(out + (size_t)r * DD + c) = v;
        }
    }
}

// mean-pool partials: sorted batch[] -> register accumulate, flush on change
#define ROWS_PB 256
__global__ void pool_kernel(const float* __restrict__ x, const int* __restrict__ batch,
                            int n, float* __restrict__ pool, int* __restrict__ pcnt) {
    int c = threadIdx.x;              // 0..127
    int r0 = blockIdx.x * ROWS_PB;
    if (r0 >= n) return;
    int r1 = min(r0 + ROWS_PB, n);
    float acc = 0.f;
    int cnt = 0;
    int gcur = batch[r0];
    for (int r = r0; r < r1; r++) {
        int g = batch[r];
        if (g != gcur) {
            atomicAdd(&pool[(size_t)gcur * DD + c], acc);
            if (c == 0) atomicAdd(&pcnt[gcur], cnt);
            acc = 0.f; cnt = 0; gcur = g;
        }
        acc += x[(size_t)r * DD + c];
        cnt++;
    }
    atomicAdd(&pool[(size_t)gcur * DD + c], acc);
    if (c == 0) atomicAdd(&pcnt[gcur], cnt);
}

// final: mean-normalize pools, concat, tiny [16,256]@[256,2] + bias
__global__ void final_kernel(const float* __restrict__ linW, const float* __restrict__ linb,
                             float* __restrict__ out) {
    int t32 = threadIdx.x;
    if (t32 >= GG * OUTD) return;
    int g = t32 / OUTD;
    int o = t32 % OUTD;
    float s = linb[o];
    for (int t = 0; t < 2; t++) {
        float ic = 1.0f / fmaxf((float)g_pcnt[t][g], 1.0f);
        const float* p = &g_pool[t][g][0];
        for (int c = 0; c < DD; c++)
            s += p[c] * ic * linW[(t * DD + c) * OUTD + o];
    }
    out[g * OUTD + o] = s;
}

// ---------------- launch ----------------
extern "C" void kernel_launch(void* const* d_in, const int* in_sizes, int n_in,
                              void* d_out, int out_size) {
    const float* x_void   = (const float*)d_in[0];
    const float* x_vessel = (const float*)d_in[1];
    const float* Wl   = (const float*)d_in[2];   // [L,2,D,D]
    const float* bl   = (const float*)d_in[3];   // [L,2,D]
    const float* Wr   = (const float*)d_in[4];   // [L,2,D,D]
    const float* linW = (const float*)d_in[5];   // [2D,OUT]
    const float* linb = (const float*)d_in[6];   // [OUT]
    const int* edge_void   = (const int*)d_in[7];   // [2,E]
    const int* edge_vessel = (const int*)d_in[8];
    const int* batch_void   = (const int*)d_in[9];  // [N]
    const int* batch_vessel = (const int*)d_in[10];

    const int n = in_sizes[9];              // 50000
    const int E = in_sizes[7] / 2;          // 800000

    float *bufA, *bufB, *meanp, *poolp;
    int *cntp, *rowp, *curp, *csrp, *pcntp;
    cudaGetSymbolAddress((void**)&bufA, g_bufA);
    cudaGetSymbolAddress((void**)&bufB, g_bufB);
    cudaGetSymbolAddress((void**)&meanp, g_mean);
    cudaGetSymbolAddress((void**)&cntp, g_cnt);
    cudaGetSymbolAddress((void**)&rowp, g_rowptr);
    cudaGetSymbolAddress((void**)&curp, g_cursor);
    cudaGetSymbolAddress((void**)&csrp, g_csr);
    cudaGetSymbolAddress((void**)&poolp, g_pool);
    cudaGetSymbolAddress((void**)&pcntp, g_pcnt);

    // zero histograms + pools (int zero == float zero bit pattern)
    zero_kernel<<<64, 256>>>((float4*)cntp, (size_t)(2 * NN) / 4);
    zero_kernel<<<4, 256>>>((float4*)poolp, (size_t)(2 * GG * DD) / 4);
    zero_kernel<<<1, 32>>>((float4*)pcntp, (size_t)(2 * GG) / 4);

    // ---- CSR build (once per type; reused across all 3 layers) ----
    const int* edges_t[2] = { edge_void, edge_vessel };
    for (int t = 0; t < 2; t++) {
        int* cnt_t = cntp + t * NN;
        int* row_t = rowp + t * (NN + 1);
        int* cur_t = curp + t * NN;
        int* csr_t = csrp + t * EE;
        count_kernel<<<512, 256>>>(edges_t[t] + E, E, cnt_t);
        scan_kernel<<<1, 1024>>>(cnt_t, n, row_t);
        copy_int_kernel<<<(n + 255) / 256, 256>>>(row_t, cur_t, n);
        fill_kernel<<<512, 256>>>(edges_t[t], edges_t[t] + E, E, cur_t, csr_t);
    }

    const float* cur[2] = { x_void, x_vessel };
    float* pingA[2] = { bufA, bufA + (size_t)NN * DD };
    float* pingB[2] = { bufB, bufB + (size_t)NN * DD };

    const int gemm_blocks = (n + BM - 1) / BM;

    for (int l = 0; l < LL; l++) {
        for (int t = 0; t < 2; t++) {
            float* nxt = (l & 1) ? pingB[t] : pingA[t];
            float* mean_t = meanp + (size_t)t * NN * DD;

            gather_mean_kernel<<<1024, 256>>>(cur[t], rowp + t * (NN + 1),
                                              csrp + t * EE, n, mean_t);

            const float* Wlp = Wl + ((size_t)(l * 2 + t)) * DD * DD;
            const float* Wrp = Wr + ((size_t)(l * 2 + t)) * DD * DD;
            const float* blp = bl + ((size_t)(l * 2 + t)) * DD;
            gemm_kernel<<<gemm_blocks, 256>>>(mean_t, cur[t], Wlp, Wrp, blp, nxt, n);
            cur[t] = nxt;
        }
    }

    // pooling
    int pblocks = (n + ROWS_PB - 1) / ROWS_PB;
    pool_kernel<<<pblocks, DD>>>(cur[0], batch_void,   n, poolp,           pcntp);
    pool_kernel<<<pblocks, DD>>>(cur[1], batch_vessel, n, poolp + GG * DD, pcntp + GG);

    final_kernel<<<1, 32>>>(linW, linb, (float*)d_out);
}

// round 6
// speedup vs baseline: 3.0810x; 1.6625x over previous
#include <cuda_runtime.h>
#include <cuda_fp16.h>
#include <cstdint>

// Problem constants (fixed by the benchmark)
#define NN   50000
#define EE   800000
#define DD   128
#define LL   3
#define GG   16
#define OUTD 2

// ---------------- static device scratch (no allocation allowed) ----------------
__device__ float g_bufA[2][(size_t)NN * DD];     // ping
__device__ float g_bufB[2][(size_t)NN * DD];     // pong
__device__ float g_mean[2][(size_t)NN * DD];     // per-type aggregated mean
__device__ int   g_cnt[2][NN];                   // in-degree histogram
__device__ int   g_rowptr[2][NN + 1];            // CSR row pointers
__device__ int   g_cursor[2][NN];                // fill cursors
__device__ int   g_csr[2][EE];                   // CSR column (src) indices
__device__ float g_pool[2][GG][DD];
__device__ int   g_pcnt[2][GG];
// transposed fused weights, fp16 hi/lo split: B'[n][k], k = [Wl rows | Wr rows]
__device__ __half g_wT_hi[(size_t)DD * 2 * DD];  // [128][256]
__device__ __half g_wT_lo[(size_t)DD * 2 * DD];

// ---------------- small helpers ----------------
__device__ __forceinline__ uint32_t smem_u32(const void* p) {
    uint32_t a;
    asm("{ .reg .u64 t; cvta.to.shared.u64 t, %1; cvt.u32.u64 %0, t; }" : "=r"(a) : "l"(p));
    return a;
}
__device__ __forceinline__ void ldsm4(uint32_t* r, uint32_t addr) {
    asm volatile("ldmatrix.sync.aligned.m8n8.x4.shared.b16 {%0,%1,%2,%3}, [%4];"
                 : "=r"(r[0]), "=r"(r[1]), "=r"(r[2]), "=r"(r[3]) : "r"(addr));
}
__device__ __forceinline__ void mma16816(float* c, const uint32_t* a, const uint32_t* b) {
    asm volatile("mma.sync.aligned.m16n8k16.row.col.f32.f16.f16.f32 "
                 "{%0,%1,%2,%3}, {%4,%5,%6,%7}, {%8,%9}, {%0,%1,%2,%3};"
                 : "+f"(c[0]), "+f"(c[1]), "+f"(c[2]), "+f"(c[3])
                 : "r"(a[0]), "r"(a[1]), "r"(a[2]), "r"(a[3]), "r"(b[0]), "r"(b[1]));
}

// ---------------- kernels ----------------

__global__ void zero_kernel(float4* p, size_t n4) {
    size_t i = blockIdx.x * (size_t)blockDim.x + threadIdx.x;
    size_t stride = (size_t)gridDim.x * blockDim.x;
    float4 z = make_float4(0.f, 0.f, 0.f, 0.f);
    for (; i < n4; i += stride) p[i] = z;
}

__global__ void count_kernel(const int* __restrict__ dst, int E, int* __restrict__ cnt) {
    int i = blockIdx.x * blockDim.x + threadIdx.x;
    int stride = gridDim.x * blockDim.x;
    for (; i < E; i += stride) atomicAdd(&cnt[dst[i]], 1);
}

__global__ void scan_kernel(const int* __restrict__ cnt, int n, int* __restrict__ rowptr) {
    __shared__ int part[1024];
    int t = threadIdx.x;
    int chunk = (n + 1023) / 1024;
    int beg = t * chunk;
    int end = min(beg + chunk, n);
    int s = 0;
    for (int i = beg; i < end; i++) s += cnt[i];
    part[t] = s;
    __syncthreads();
    for (int off = 1; off < 1024; off <<= 1) {
        int v = (t >= off) ? part[t - off] : 0;
        __syncthreads();
        part[t] += v;
        __syncthreads();
    }
    int run = (t == 0) ? 0 : part[t - 1];
    for (int i = beg; i < end; i++) { rowptr[i] = run; run += cnt[i]; }
    if (t == 0) rowptr[n] = part[1023];
}

__global__ void copy_int_kernel(const int* __restrict__ src, int* __restrict__ dst, int n) {
    int i = blockIdx.x * blockDim.x + threadIdx.x;
    if (i < n) dst[i] = src[i];
}

__global__ void fill_kernel(const int* __restrict__ src, const int* __restrict__ dst,
                            int E, int* __restrict__ cursor, int* __restrict__ csr) {
    int i = blockIdx.x * blockDim.x + threadIdx.x;
    int stride = gridDim.x * blockDim.x;
    for (; i < E; i += stride) {
        int d = dst[i];
        int pos = atomicAdd(&cursor[d], 1);
        csr[pos] = src[i];
    }
}

// warp-per-node gather + mean
__global__ void gather_mean_kernel(const float* __restrict__ x,
                                   const int* __restrict__ rowptr,
                                   const int* __restrict__ csr,
                                   int n, float* __restrict__ mean) {
    int warp = (blockIdx.x * blockDim.x + threadIdx.x) >> 5;
    int lane = threadIdx.x & 31;
    int nwarps = (gridDim.x * blockDim.x) >> 5;
    const float4* x4 = (const float4*)x;
    for (int node = warp; node < n; node += nwarps) {
        int b = rowptr[node];
        int e = rowptr[node + 1];
        float4 a0 = make_float4(0.f, 0.f, 0.f, 0.f);
        float4 a1 = a0;
        int j = b;
        for (; j + 1 < e; j += 2) {
            int s0 = __ldg(&csr[j]);
            int s1 = __ldg(&csr[j + 1]);
            float4 v0 = x4[(size_t)s0 * 32 + lane];
            float4 v1 = x4[(size_t)s1 * 32 + lane];
            a0.x += v0.x; a0.y += v0.y; a0.z += v0.z; a0.w += v0.w;
            a1.x += v1.x; a1.y += v1.y; a1.z += v1.z; a1.w += v1.w;
        }
        if (j < e) {
            int s0 = __ldg(&csr[j]);
            float4 v0 = x4[(size_t)s0 * 32 + lane];
            a0.x += v0.x; a0.y += v0.y; a0.z += v0.z; a0.w += v0.w;
        }
        float ic = 1.0f / (float)max(e - b, 1);
        float4 r;
        r.x = (a0.x + a1.x) * ic;
        r.y = (a0.y + a1.y) * ic;
        r.z = (a0.z + a1.z) * ic;
        r.w = (a0.w + a1.w) * ic;
        ((float4*)mean)[(size_t)node * 32 + lane] = r;
    }
}

// weight prep: W'[k][n] -> B'[n][k] fp16 hi/lo, plain [128][256] layout
__global__ void wprep_kernel(const float* __restrict__ Wlp, const float* __restrict__ Wrp) {
    int nrow = blockIdx.x;     // 0..127 (output col = B' row)
    int k = threadIdx.x;       // 0..127
#pragma unroll
    for (int m = 0; m < 2; m++) {
        const float* W = m ? Wrp : Wlp;
        float v = W[(size_t)k * DD + nrow];
        __half h = __float2half_rn(v);
        float r = v - __half2float(h);
        __half l = __float2half_rn(r);
        g_wT_hi[(size_t)nrow * 256 + m * DD + k] = h;
        g_wT_lo[(size_t)nrow * 256 + m * DD + k] = l;
    }
}

// Tensor-core (legacy mma.sync) fused SAGE GEMM:
//   out = relu([mean|x] @ [Wl;Wr] + bias)  via fp16-split 3-product accumulation.
#define AST 40   // padded smem row stride (halfs) => 80B, conflict-free ldmatrix
__global__ __launch_bounds__(256, 2)
void gemm_mma_kernel(const float* __restrict__ mean, const float* __restrict__ xin,
                     const float* __restrict__ bias, float* __restrict__ out, int n) {
    __shared__ __align__(16) __half Ah[128 * AST];
    __shared__ __align__(16) __half Al[128 * AST];
    __shared__ __align__(16) __half Bh[128 * AST];
    __shared__ __align__(16) __half Bl[128 * AST];

    int tid = threadIdx.x, wid = tid >> 5, lane = tid & 31;
    int row0 = blockIdx.x * 128;
    int wm = wid & 3;          // 4 m-blocks of 32 rows
    int wn = wid >> 2;         // 2 n-blocks of 64 cols

    float acc[2][8][4];
#pragma unroll
    for (int a = 0; a < 2; a++)
#pragma unroll
        for (int b = 0; b < 8; b++)
#pragma unroll
            for (int c = 0; c < 4; c++) acc[a][b][c] = 0.f;

    uint32_t ahB = smem_u32(Ah), alB = smem_u32(Al);
    uint32_t bhB = smem_u32(Bh), blB = smem_u32(Bl);

    // ldmatrix per-lane invariant coordinates
    int a_row = wm * 32 + (lane & 7) + ((lane >> 3) & 1) * 8;  // + mt*16
    int a_col = (lane >> 4) * 8;                               // + k0
    int b_row = wn * 64 + (lane & 7) + (lane >> 4) * 8;        // + p*16
    int b_col = ((lane >> 3) & 1) * 8;                         // + k0

    // fill coordinates
    int frow = tid >> 1;
    int fcol = (tid & 1) * 16;

    for (int kb = 0; kb < 8; kb++) {
        // ---- fill A tile (fp32 -> fp16 hi/lo split) ----
        {
            const float* S = (kb < 4) ? mean : xin;
            int kc = (kb & 3) * 32;
            int gr = row0 + frow;
            const float4* s4 = (const float4*)(S + (size_t)gr * DD + kc + fcol);
            __half* ah = Ah + frow * AST + fcol;
            __half* al = Al + frow * AST + fcol;
#pragma unroll
            for (int i = 0; i < 4; i++) {
                float4 v = make_float4(0.f, 0.f, 0.f, 0.f);
                if (gr < n) v = s4[i];
                __half hx = __float2half_rn(v.x), hy = __float2half_rn(v.y);
                __half hz = __float2half_rn(v.z), hw = __float2half_rn(v.w);
                *(half2*)(ah + i * 4)     = __halves2half2(hx, hy);
                *(half2*)(ah + i * 4 + 2) = __halves2half2(hz, hw);
                *(half2*)(al + i * 4)     = __halves2half2(
                    __float2half_rn(v.x - __half2float(hx)),
                    __float2half_rn(v.y - __half2float(hy)));
                *(half2*)(al + i * 4 + 2) = __halves2half2(
                    __float2half_rn(v.z - __half2float(hz)),
                    __float2half_rn(v.w - __half2float(hw)));
            }
        }
        // ---- fill B tile (copy pre-split fp16) ----
        {
            int bn = tid >> 1;
            size_t goff = (size_t)bn * 256 + kb * 32 + fcol;
            const int4* gh = (const int4*)(g_wT_hi + goff);
            const int4* gl = (const int4*)(g_wT_lo + goff);
            int4* sh = (int4*)(Bh + bn * AST + fcol);
            int4* sl = (int4*)(Bl + bn * AST + fcol);
            sh[0] = gh[0]; sh[1] = gh[1];
            sl[0] = gl[0]; sl[1] = gl[1];
        }
        __syncthreads();

#pragma unroll
        for (int ks = 0; ks < 2; ks++) {
            int k0 = ks * 16;
            uint32_t ah[2][4], al2[2][4], bf[16];
            // A hi frags (2 m-tiles)
#pragma unroll
            for (int mt = 0; mt < 2; mt++)
                ldsm4(ah[mt], ahB + ((a_row + mt * 16) * AST + a_col + k0) * 2);
            // B hi frags (4 x4 loads = 8 n-tiles)
#pragma unroll
            for (int p = 0; p < 4; p++)
                ldsm4(&bf[p * 4], bhB + ((b_row + p * 16) * AST + b_col + k0) * 2);
            // P1: ah x bh
#pragma unroll
            for (int mt = 0; mt < 2; mt++)
#pragma unroll
                for (int p = 0; p < 4; p++) {
                    mma16816(acc[mt][p * 2 + 0], ah[mt], &bf[p * 4 + 0]);
                    mma16816(acc[mt][p * 2 + 1], ah[mt], &bf[p * 4 + 2]);
                }
            // A lo frags
#pragma unroll
            for (int mt = 0; mt < 2; mt++)
                ldsm4(al2[mt], alB + ((a_row + mt * 16) * AST + a_col + k0) * 2);
            // P2: al x bh
#pragma unroll
            for (int mt = 0; mt < 2; mt++)
#pragma unroll
                for (int p = 0; p < 4; p++) {
                    mma16816(acc[mt][p * 2 + 0], al2[mt], &bf[p * 4 + 0]);
                    mma16816(acc[mt][p * 2 + 1], al2[mt], &bf[p * 4 + 2]);
                }
            // B lo frags (reuse bf regs)
#pragma unroll
            for (int p = 0; p < 4; p++)
                ldsm4(&bf[p * 4], blB + ((b_row + p * 16) * AST + b_col + k0) * 2);
            // P3: ah x bl
#pragma unroll
            for (int mt = 0; mt < 2; mt++)
#pragma unroll
                for (int p = 0; p < 4; p++) {
                    mma16816(acc[mt][p * 2 + 0], ah[mt], &bf[p * 4 + 0]);
                    mma16816(acc[mt][p * 2 + 1], ah[mt], &bf[p * 4 + 2]);
                }
        }
        __syncthreads();
    }

    // ---- epilogue: bias + relu ----
#pragma unroll
    for (int mt = 0; mt < 2; mt++) {
#pragma unroll
        for (int rr = 0; rr < 2; rr++) {
            int row = row0 + wm * 32 + mt * 16 + (lane >> 2) + rr * 8;
            if (row >= n) continue;
            float* o = out + (size_t)row * DD;
#pragma unroll
            for (int nt = 0; nt < 8; nt++) {
                int col = wn * 64 + nt * 8 + (lane & 3) * 2;
                float2 v;
                v.x = fmaxf(acc[mt][nt][rr * 2 + 0] + __ldg(&bias[col + 0]), 0.f);
                v.y = fmaxf(acc[mt][nt][rr * 2 + 1] + __ldg(&bias[col + 1]), 0.f);
                *(float2*)(o + col) = v;
            }
        }
    }
}

// mean-pool partials: sorted batch[] -> register accumulate, flush on change
#define ROWS_PB 256
__global__ void pool_kernel(const float* __restrict__ x, const int* __restrict__ batch,
                            int n, float* __restrict__ pool, int* __restrict__ pcnt) {
    int c = threadIdx.x;              // 0..127
    int r0 = blockIdx.x * ROWS_PB;
    if (r0 >= n) return;
    int r1 = min(r0 + ROWS_PB, n);
    float acc = 0.f;
    int cnt = 0;
    int gcur = batch[r0];
    for (int r = r0; r < r1; r++) {
        int g = batch[r];
        if (g != gcur) {
            atomicAdd(&pool[(size_t)gcur * DD + c], acc);
            if (c == 0) atomicAdd(&pcnt[gcur], cnt);
            acc = 0.f; cnt = 0; gcur = g;
        }
        acc += x[(size_t)r * DD + c];
        cnt++;
    }
    atomicAdd(&pool[(size_t)gcur * DD + c], acc);
    if (c == 0) atomicAdd(&pcnt[gcur], cnt);
}

__global__ void final_kernel(const float* __restrict__ linW, const float* __restrict__ linb,
                             float* __restrict__ out) {
    int t32 = threadIdx.x;
    if (t32 >= GG * OUTD) return;
    int g = t32 / OUTD;
    int o = t32 % OUTD;
    float s = linb[o];
    for (int t = 0; t < 2; t++) {
        float ic = 1.0f / fmaxf((float)g_pcnt[t][g], 1.0f);
        const float* p = &g_pool[t][g][0];
        for (int c = 0; c < DD; c++)
            s += p[c] * ic * linW[(t * DD + c) * OUTD + o];
    }
    out[g * OUTD + o] = s;
}

// ---------------- launch ----------------
extern "C" void kernel_launch(void* const* d_in, const int* in_sizes, int n_in,
                              void* d_out, int out_size) {
    const float* x_void   = (const float*)d_in[0];
    const float* x_vessel = (const float*)d_in[1];
    const float* Wl   = (const float*)d_in[2];   // [L,2,D,D]
    const float* bl   = (const float*)d_in[3];   // [L,2,D]
    const float* Wr   = (const float*)d_in[4];   // [L,2,D,D]
    const float* linW = (const float*)d_in[5];   // [2D,OUT]
    const float* linb = (const float*)d_in[6];   // [OUT]
    const int* edge_void   = (const int*)d_in[7];   // [2,E]
    const int* edge_vessel = (const int*)d_in[8];
    const int* batch_void   = (const int*)d_in[9];  // [N]
    const int* batch_vessel = (const int*)d_in[10];

    const int n = in_sizes[9];              // 50000
    const int E = in_sizes[7] / 2;          // 800000

    float *bufA, *bufB, *meanp, *poolp;
    int *cntp, *rowp, *curp, *csrp, *pcntp;
    cudaGetSymbolAddress((void**)&bufA, g_bufA);
    cudaGetSymbolAddress((void**)&bufB, g_bufB);
    cudaGetSymbolAddress((void**)&meanp, g_mean);
    cudaGetSymbolAddress((void**)&cntp, g_cnt);
    cudaGetSymbolAddress((void**)&rowp, g_rowptr);
    cudaGetSymbolAddress((void**)&curp, g_cursor);
    cudaGetSymbolAddress((void**)&csrp, g_csr);
    cudaGetSymbolAddress((void**)&poolp, g_pool);
    cudaGetSymbolAddress((void**)&pcntp, g_pcnt);

    // zero histograms + pools
    zero_kernel<<<64, 256>>>((float4*)cntp, (size_t)(2 * NN) / 4);
    zero_kernel<<<4, 256>>>((float4*)poolp, (size_t)(2 * GG * DD) / 4);
    zero_kernel<<<1, 32>>>((float4*)pcntp, (size_t)(2 * GG) / 4);

    // ---- CSR build (once per type; reused across all 3 layers) ----
    const int* edges_t[2] = { edge_void, edge_vessel };
    for (int t = 0; t < 2; t++) {
        int* cnt_t = cntp + t * NN;
        int* row_t = rowp + t * (NN + 1);
        int* cur_t = curp + t * NN;
        int* csr_t = csrp + t * EE;
        count_kernel<<<512, 256>>>(edges_t[t] + E, E, cnt_t);
        scan_kernel<<<1, 1024>>>(cnt_t, n, row_t);
        copy_int_kernel<<<(n + 255) / 256, 256>>>(row_t, cur_t, n);
        fill_kernel<<<512, 256>>>(edges_t[t], edges_t[t] + E, E, cur_t, csr_t);
    }

    const float* cur[2] = { x_void, x_vessel };
    float* pingA[2] = { bufA, bufA + (size_t)NN * DD };
    float* pingB[2] = { bufB, bufB + (size_t)NN * DD };

    const int gemm_blocks = (n + 127) / 128;

    for (int l = 0; l < LL; l++) {
        for (int t = 0; t < 2; t++) {
            float* nxt = (l & 1) ? pingB[t] : pingA[t];
            float* mean_t = meanp + (size_t)t * NN * DD;

            gather_mean_kernel<<<1024, 256>>>(cur[t], rowp + t * (NN + 1),
                                              csrp + t * EE, n, mean_t);

            const float* Wlp = Wl + ((size_t)(l * 2 + t)) * DD * DD;
            const float* Wrp = Wr + ((size_t)(l * 2 + t)) * DD * DD;
            const float* blp = bl + ((size_t)(l * 2 + t)) * DD;
            wprep_kernel<<<128, 128>>>(Wlp, Wrp);
            gemm_mma_kernel<<<gemm_blocks, 256>>>(mean_t, cur[t], blp, nxt, n);
            cur[t] = nxt;
        }
    }

    // pooling
    int pblocks = (n + ROWS_PB - 1) / ROWS_PB;
    pool_kernel<<<pblocks, DD>>>(cur[0], batch_void,   n, poolp,           pcntp);
    pool_kernel<<<pblocks, DD>>>(cur[1], batch_vessel, n, poolp + GG * DD, pcntp + GG);

    final_kernel<<<1, 32>>>(linW, linb, (float*)d_out);
}

// round 7
// speedup vs baseline: 3.0828x; 1.0006x over previous
#include <cuda_runtime.h>
#include <cuda_fp16.h>
#include <cstdint>

// Problem constants (fixed by the benchmark)
#define NN   50000
#define EE   800000
#define DD   128
#define LL   3
#define GG   16
#define OUTD 2

// ---------------- static device scratch (no allocation allowed) ----------------
__device__ float g_bufA[2][(size_t)NN * DD];     // ping
__device__ float g_bufB[2][(size_t)NN * DD];     // pong
__device__ int   g_cnt[2][NN];                   // in-degree histogram
__device__ int   g_rowptr[2][NN + 1];            // CSR row pointers
__device__ int   g_cursor[2][NN];                // fill cursors
__device__ int   g_csr[2][EE];                   // CSR column (src) indices
__device__ float g_pool[2][GG][DD];
__device__ int   g_pcnt[2][GG];
// transposed fused weights for ALL layers/types, fp16 hi/lo: [L*2][128][256]
__device__ __half g_wT_hi[6 * 32768];
__device__ __half g_wT_lo[6 * 32768];

// ---------------- small helpers ----------------
__device__ __forceinline__ uint32_t smem_u32(const void* p) {
    uint32_t a;
    asm("{ .reg .u64 t; cvta.to.shared.u64 t, %1; cvt.u32.u64 %0, t; }" : "=r"(a) : "l"(p));
    return a;
}
__device__ __forceinline__ void ldsm4(uint32_t* r, uint32_t addr) {
    asm volatile("ldmatrix.sync.aligned.m8n8.x4.shared.b16 {%0,%1,%2,%3}, [%4];"
                 : "=r"(r[0]), "=r"(r[1]), "=r"(r[2]), "=r"(r[3]) : "r"(addr));
}
__device__ __forceinline__ void mma16816(float* c, const uint32_t* a, const uint32_t* b) {
    asm volatile("mma.sync.aligned.m16n8k16.row.col.f32.f16.f16.f32 "
                 "{%0,%1,%2,%3}, {%4,%5,%6,%7}, {%8,%9}, {%0,%1,%2,%3};"
                 : "+f"(c[0]), "+f"(c[1]), "+f"(c[2]), "+f"(c[3])
                 : "r"(a[0]), "r"(a[1]), "r"(a[2]), "r"(a[3]), "r"(b[0]), "r"(b[1]));
}

// ---------------- setup kernels (merged, one launch each) ----------------

// zero cnt + pool + pcnt in one launch
__global__ void zero_all_kernel() {
    int i = blockIdx.x * blockDim.x + threadIdx.x;
    int stride = gridDim.x * blockDim.x;
    int* cnt = &g_cnt[0][0];
    for (int j = i; j < 2 * NN; j += stride) cnt[j] = 0;
    float* pool = &g_pool[0][0][0];
    for (int j = i; j < 2 * GG * DD; j += stride) pool[j] = 0.f;
    int* pcnt = &g_pcnt[0][0];
    for (int j = i; j < 2 * GG; j += stride) pcnt[j] = 0;
}

// in-degree histogram, both types
__global__ void count_both_kernel(const int* __restrict__ dst0,
                                  const int* __restrict__ dst1, int E) {
    int i = blockIdx.x * blockDim.x + threadIdx.x;
    int stride = gridDim.x * blockDim.x;
    for (; i < 2 * E; i += stride) {
        if (i < E) atomicAdd(&g_cnt[0][dst0[i]], 1);
        else       atomicAdd(&g_cnt[1][dst1[i - E]], 1);
    }
}

// per-type exclusive scan; also seeds the fill cursor (blockIdx.x = type)
__global__ void scan_both_kernel(int n) {
    __shared__ int part[1024];
    int ty = blockIdx.x;
    const int* cnt = g_cnt[ty];
    int* rowptr = g_rowptr[ty];
    int* cursor = g_cursor[ty];
    int t = threadIdx.x;
    int chunk = (n + 1023) / 1024;
    int beg = t * chunk;
    int end = min(beg + chunk, n);
    int s = 0;
    for (int i = beg; i < end; i++) s += cnt[i];
    part[t] = s;
    __syncthreads();
    for (int off = 1; off < 1024; off <<= 1) {
        int v = (t >= off) ? part[t - off] : 0;
        __syncthreads();
        part[t] += v;
        __syncthreads();
    }
    int run = (t == 0) ? 0 : part[t - 1];
    for (int i = beg; i < end; i++) {
        rowptr[i] = run;
        cursor[i] = run;
        run += cnt[i];
    }
    if (t == 0) rowptr[n] = part[1023];
}

// CSR fill, both types
__global__ void fill_both_kernel(const int* __restrict__ e0,
                                 const int* __restrict__ e1, int E) {
    int i = blockIdx.x * blockDim.x + threadIdx.x;
    int stride = gridDim.x * blockDim.x;
    for (; i < 2 * E; i += stride) {
        int t = (i >= E);
        const int* e = t ? e1 : e0;
        int j = t ? i - E : i;
        int d = e[E + j];
        int pos = atomicAdd(&g_cursor[t][d], 1);
        g_csr[t][pos] = e[j];
    }
}

// prep ALL L*2 weight matrices once: W'[k][n] -> B'[n][k] fp16 hi/lo
__global__ void wprep_all_kernel(const float* __restrict__ Wl,
                                 const float* __restrict__ Wr) {
    int lt = blockIdx.y;       // 0..5 = l*2+t
    int nrow = blockIdx.x;     // 0..127
    int k = threadIdx.x;       // 0..127
    size_t wb = (size_t)lt * DD * DD;
    size_t ob = (size_t)lt * 32768 + (size_t)nrow * 256;
#pragma unroll
    for (int m = 0; m < 2; m++) {
        const float* W = m ? Wr : Wl;
        float v = W[wb + (size_t)k * DD + nrow];
        __half h = __float2half_rn(v);
        __half l = __float2half_rn(v - __half2float(h));
        g_wT_hi[ob + m * DD + k] = h;
        g_wT_lo[ob + m * DD + k] = l;
    }
}

// ---------------- fused layer kernel: gather(mean)->smem + split-fp16 MMA GEMM ----
// out = relu([mean|x] @ [Wl;Wr] + bias), per 128-row tile, both types in one grid.
#define AST   40                     // padded GEMM tile stride (halfs), conflict-free
#define MST   132                    // mean smem stride (floats), conflict-free
#define SMEM_LAYER (128 * MST * 4 + 4 * 128 * AST * 2)   // 67584 + 40960 = 108544

__global__ __launch_bounds__(256, 2)
void layer_kernel(const float* __restrict__ x0, const float* __restrict__ x1,
                  float* __restrict__ out0, float* __restrict__ out1,
                  const __half* __restrict__ wHi, const __half* __restrict__ wLo,
                  const float* __restrict__ bias,   // [2][128]
                  int n, int tiles_per_type) {
    extern __shared__ __align__(16) char smem[];
    float* meanS = (float*)smem;
    __half* Ah = (__half*)(smem + 128 * MST * 4);
    __half* Al = Ah + 128 * AST;
    __half* Bh = Al + 128 * AST;
    __half* Bl = Bh + 128 * AST;

    int tid = threadIdx.x, wid = tid >> 5, lane = tid & 31;
    int bt = blockIdx.x / tiles_per_type;           // type
    int tile = blockIdx.x - bt * tiles_per_type;
    int row0 = tile * 128;

    const float* xin = bt ? x1 : x0;
    float* out = bt ? out1 : out0;
    const int* rowptr = g_rowptr[bt];
    const int* csr = g_csr[bt];
    const __half* whi = wHi + (size_t)bt * 32768;
    const __half* wlo = wLo + (size_t)bt * 32768;
    const float* bias_t = bias + bt * DD;

    // ---- phase 1: gather mean for this tile into smem ----
    {
        const float4* x4 = (const float4*)xin;
#pragma unroll 1
        for (int r = 0; r < 16; r++) {
            int lrow = wid * 16 + r;
            int node = row0 + lrow;
            float4 a0 = make_float4(0.f, 0.f, 0.f, 0.f);
            float4 a1 = a0;
            if (node < n) {
                int b = rowptr[node];
                int e = rowptr[node + 1];
                int j = b;
                for (; j + 1 < e; j += 2) {
                    int s0 = __ldg(&csr[j]);
                    int s1 = __ldg(&csr[j + 1]);
                    float4 v0 = x4[(size_t)s0 * 32 + lane];
                    float4 v1 = x4[(size_t)s1 * 32 + lane];
                    a0.x += v0.x; a0.y += v0.y; a0.z += v0.z; a0.w += v0.w;
                    a1.x += v1.x; a1.y += v1.y; a1.z += v1.z; a1.w += v1.w;
                }
                if (j < e) {
                    int s0 = __ldg(&csr[j]);
                    float4 v0 = x4[(size_t)s0 * 32 + lane];
                    a0.x += v0.x; a0.y += v0.y; a0.z += v0.z; a0.w += v0.w;
                }
                float ic = 1.0f / (float)max(e - b, 1);
                a0.x = (a0.x + a1.x) * ic;
                a0.y = (a0.y + a1.y) * ic;
                a0.z = (a0.z + a1.z) * ic;
                a0.w = (a0.w + a1.w) * ic;
            }
            *(float4*)(meanS + lrow * MST + lane * 4) = a0;
        }
    }
    __syncthreads();

    // ---- phase 2: GEMM C = [mean|x] @ W' (fp16-split, 3-product) ----
    int wm = wid & 3;          // 4 m-blocks of 32 rows
    int wn = wid >> 2;         // 2 n-blocks of 64 cols

    float acc[2][8][4];
#pragma unroll
    for (int a = 0; a < 2; a++)
#pragma unroll
        for (int b = 0; b < 8; b++)
#pragma unroll
            for (int c = 0; c < 4; c++) acc[a][b][c] = 0.f;

    uint32_t ahB = smem_u32(Ah), alB = smem_u32(Al);
    uint32_t bhB = smem_u32(Bh), blB = smem_u32(Bl);

    int a_row = wm * 32 + (lane & 7) + ((lane >> 3) & 1) * 8;  // + mt*16
    int a_col = (lane >> 4) * 8;                               // + k0
    int b_row = wn * 64 + (lane & 7) + (lane >> 4) * 8;        // + p*16
    int b_col = ((lane >> 3) & 1) * 8;                         // + k0

    int frow = tid >> 1;
    int fcol = (tid & 1) * 16;

    for (int kb = 0; kb < 8; kb++) {
        // ---- fill A tile (fp32 -> fp16 hi/lo split) ----
        {
            int kc = (kb & 3) * 32;
            int gr = row0 + frow;
            __half* ah = Ah + frow * AST + fcol;
            __half* al = Al + frow * AST + fcol;
#pragma unroll
            for (int i = 0; i < 4; i++) {
                float4 v;
                if (kb < 4) {
                    v = *(const float4*)(meanS + frow * MST + kc + fcol + i * 4);
                } else {
                    v = make_float4(0.f, 0.f, 0.f, 0.f);
                    if (gr < n)
                        v = *(const float4*)(xin + (size_t)gr * DD + kc + fcol + i * 4);
                }
                __half hx = __float2half_rn(v.x), hy = __float2half_rn(v.y);
                __half hz = __float2half_rn(v.z), hw = __float2half_rn(v.w);
                *(half2*)(ah + i * 4)     = __halves2half2(hx, hy);
                *(half2*)(ah + i * 4 + 2) = __halves2half2(hz, hw);
                *(half2*)(al + i * 4)     = __halves2half2(
                    __float2half_rn(v.x - __half2float(hx)),
                    __float2half_rn(v.y - __half2float(hy)));
                *(half2*)(al + i * 4 + 2) = __halves2half2(
                    __float2half_rn(v.z - __half2float(hz)),
                    __float2half_rn(v.w - __half2float(hw)));
            }
        }
        // ---- fill B tile (copy pre-split fp16) ----
        {
            int bn = tid >> 1;
            size_t goff = (size_t)bn * 256 + kb * 32 + fcol;
            const int4* gh = (const int4*)(whi + goff);
            const int4* gl = (const int4*)(wlo + goff);
            int4* sh = (int4*)(Bh + bn * AST + fcol);
            int4* sl = (int4*)(Bl + bn * AST + fcol);
            sh[0] = gh[0]; sh[1] = gh[1];
            sl[0] = gl[0]; sl[1] = gl[1];
        }
        __syncthreads();

#pragma unroll
        for (int ks = 0; ks < 2; ks++) {
            int k0 = ks * 16;
            uint32_t ah[2][4], al2[2][4], bf[16];
#pragma unroll
            for (int mt = 0; mt < 2; mt++)
                ldsm4(ah[mt], ahB + ((a_row + mt * 16) * AST + a_col + k0) * 2);
#pragma unroll
            for (int p = 0; p < 4; p++)
                ldsm4(&bf[p * 4], bhB + ((b_row + p * 16) * AST + b_col + k0) * 2);
            // P1: ah x bh
#pragma unroll
            for (int mt = 0; mt < 2; mt++)
#pragma unroll
                for (int p = 0; p < 4; p++) {
                    mma16816(acc[mt][p * 2 + 0], ah[mt], &bf[p * 4 + 0]);
                    mma16816(acc[mt][p * 2 + 1], ah[mt], &bf[p * 4 + 2]);
                }
#pragma unroll
            for (int mt = 0; mt < 2; mt++)
                ldsm4(al2[mt], alB + ((a_row + mt * 16) * AST + a_col + k0) * 2);
            // P2: al x bh
#pragma unroll
            for (int mt = 0; mt < 2; mt++)
#pragma unroll
                for (int p = 0; p < 4; p++) {
                    mma16816(acc[mt][p * 2 + 0], al2[mt], &bf[p * 4 + 0]);
                    mma16816(acc[mt][p * 2 + 1], al2[mt], &bf[p * 4 + 2]);
                }
#pragma unroll
            for (int p = 0; p < 4; p++)
                ldsm4(&bf[p * 4], blB + ((b_row + p * 16) * AST + b_col + k0) * 2);
            // P3: ah x bl
#pragma unroll
            for (int mt = 0; mt < 2; mt++)
#pragma unroll
                for (int p = 0; p < 4; p++) {
                    mma16816(acc[mt][p * 2 + 0], ah[mt], &bf[p * 4 + 0]);
                    mma16816(acc[mt][p * 2 + 1], ah[mt], &bf[p * 4 + 2]);
                }
        }
        __syncthreads();
    }

    // ---- epilogue: bias + relu ----
#pragma unroll
    for (int mt = 0; mt < 2; mt++) {
#pragma unroll
        for (int rr = 0; rr < 2; rr++) {
            int row = row0 + wm * 32 + mt * 16 + (lane >> 2) + rr * 8;
            if (row >= n) continue;
            float* o = out + (size_t)row * DD;
#pragma unroll
            for (int nt = 0; nt < 8; nt++) {
                int col = wn * 64 + nt * 8 + (lane & 3) * 2;
                float2 v;
                v.x = fmaxf(acc[mt][nt][rr * 2 + 0] + __ldg(&bias_t[col + 0]), 0.f);
                v.y = fmaxf(acc[mt][nt][rr * 2 + 1] + __ldg(&bias_t[col + 1]), 0.f);
                *(float2*)(o + col) = v;
            }
        }
    }
}

// ---------------- pooling + head ----------------
#define ROWS_PB 256
__global__ void pool_both_kernel(const float* __restrict__ xa, const float* __restrict__ xb,
                                 const int* __restrict__ ba, const int* __restrict__ bb,
                                 int n, int pblocks) {
    int t = (blockIdx.x >= pblocks);
    int blk = t ? blockIdx.x - pblocks : blockIdx.x;
    const float* x = t ? xb : xa;
    const int* batch = t ? bb : ba;
    float* pool = &g_pool[t][0][0];
    int* pcnt = g_pcnt[t];

    int c = threadIdx.x;              // 0..127
    int r0 = blk * ROWS_PB;
    if (r0 >= n) return;
    int r1 = min(r0 + ROWS_PB, n);
    float acc = 0.f;
    int cnt = 0;
    int gcur = batch[r0];
    for (int r = r0; r < r1; r++) {
        int g = batch[r];
        if (g != gcur) {
            atomicAdd(&pool[(size_t)gcur * DD + c], acc);
            if (c == 0) atomicAdd(&pcnt[gcur], cnt);
            acc = 0.f; cnt = 0; gcur = g;
        }
        acc += x[(size_t)r * DD + c];
        cnt++;
    }
    atomicAdd(&pool[(size_t)gcur * DD + c], acc);
    if (c == 0) atomicAdd(&pcnt[gcur], cnt);
}

__global__ void final_kernel(const float* __restrict__ linW, const float* __restrict__ linb,
                             float* __restrict__ out) {
    int t32 = threadIdx.x;
    if (t32 >= GG * OUTD) return;
    int g = t32 / OUTD;
    int o = t32 % OUTD;
    float s = linb[o];
    for (int t = 0; t < 2; t++) {
        float ic = 1.0f / fmaxf((float)g_pcnt[t][g], 1.0f);
        const float* p = &g_pool[t][g][0];
        for (int c = 0; c < DD; c++)
            s += p[c] * ic * linW[(t * DD + c) * OUTD + o];
    }
    out[g * OUTD + o] = s;
}

// ---------------- launch ----------------
extern "C" void kernel_launch(void* const* d_in, const int* in_sizes, int n_in,
                              void* d_out, int out_size) {
    const float* x_void   = (const float*)d_in[0];
    const float* x_vessel = (const float*)d_in[1];
    const float* Wl   = (const float*)d_in[2];   // [L,2,D,D]
    const float* bl   = (const float*)d_in[3];   // [L,2,D]
    const float* Wr   = (const float*)d_in[4];   // [L,2,D,D]
    const float* linW = (const float*)d_in[5];   // [2D,OUT]
    const float* linb = (const float*)d_in[6];   // [OUT]
    const int* edge_void   = (const int*)d_in[7];   // [2,E]
    const int* edge_vessel = (const int*)d_in[8];
    const int* batch_void   = (const int*)d_in[9];  // [N]
    const int* batch_vessel = (const int*)d_in[10];

    const int n = in_sizes[9];              // 50000
    const int E = in_sizes[7] / 2;          // 800000

    float *bufA, *bufB;
    __half *whiP, *wloP;
    cudaGetSymbolAddress((void**)&bufA, g_bufA);
    cudaGetSymbolAddress((void**)&bufB, g_bufB);
    cudaGetSymbolAddress((void**)&whiP, g_wT_hi);
    cudaGetSymbolAddress((void**)&wloP, g_wT_lo);

    static bool attr_set = false;
    cudaFuncSetAttribute(layer_kernel,
                         cudaFuncAttributeMaxDynamicSharedMemorySize, SMEM_LAYER);
    (void)attr_set;

    // setup (5 launches)
    zero_all_kernel<<<128, 256>>>();
    count_both_kernel<<<1024, 256>>>(edge_void + E, edge_vessel + E, E);
    scan_both_kernel<<<2, 1024>>>(n);
    fill_both_kernel<<<1024, 256>>>(edge_void, edge_vessel, E);
    {
        dim3 g(128, 6);
        wprep_all_kernel<<<g, 128>>>(Wl, Wr);
    }

    const int tiles = (n + 127) / 128;
    const float* c0 = x_void;
    const float* c1 = x_vessel;
    float* a0 = bufA;                      float* a1 = bufA + (size_t)NN * DD;
    float* b0 = bufB;                      float* b1 = bufB + (size_t)NN * DD;

    for (int l = 0; l < LL; l++) {
        float* o0 = (l & 1) ? b0 : a0;
        float* o1 = (l & 1) ? b1 : a1;
        layer_kernel<<<2 * tiles, 256, SMEM_LAYER>>>(
            c0, c1, o0, o1,
            whiP + (size_t)l * 2 * 32768, wloP + (size_t)l * 2 * 32768,
            bl + (size_t)l * 2 * DD, n, tiles);
        c0 = o0; c1 = o1;
    }

    // pooling (1 launch) + head (1 launch)
    int pblocks = (n + ROWS_PB - 1) / ROWS_PB;
    pool_both_kernel<<<2 * pblocks, DD>>>(c0, c1, batch_void, batch_vessel, n, pblocks);
    final_kernel<<<1, 32>>>(linW, linb, (float*)d_out);
}